// round 3
// baseline (speedup 1.0000x reference)
#include <cuda_runtime.h>
#include <cuda_bf16.h>

// Gather: out[i, y, x, c] = logits[i * N_SP + segments[i, y, x], c]
//   logits:   [16*512, 5] fp32 (10 KB per image, staged in smem)
//   segments: [16, 512, 512] int32
//   out:      [16, 512, 512, 5] fp32
//
// R3: same smem-gather structure as R2, but
//  - one integer division per THREAD (incremental p/r update across iters)
//  - per-float channel/pixel selection via predicated select (no div/mod)
//  - all seg LDGs hoisted ahead of the gather phase (MLP ~10)
//  - 512-thread blocks for better SM residency

#define N_IMG 16
#define SIZE  512
#define N_SP  512
#define WAY   5
#define PIX_PER_IMG    (SIZE * SIZE)           // 262144
#define FLOATS_PER_IMG (PIX_PER_IMG * WAY)     // 1310720
#define VEC_PER_IMG    (FLOATS_PER_IMG / 4)    // 327680
#define LOGITS_PER_IMG (N_SP * WAY)            // 2560 floats = 10 KB

#define THREADS 512
#define BLOCKS_PER_IMG 128
#define ITERS 5                                // 512*128*5 = 327680 = VEC_PER_IMG
#define VEC_PER_BLOCK (THREADS * ITERS)        // 2560

// float-index step per iteration = 4*THREADS = 2048 = 5*409 + 3
#define P_STEP 409
#define R_STEP 3

__global__ void __launch_bounds__(THREADS)
sp_gather_kernel3(const float* __restrict__ logits,
                  const int* __restrict__ seg,
                  float4* __restrict__ out)
{
    __shared__ float s_logits[LOGITS_PER_IMG];

    const int img = blockIdx.y;
    const int blk = blockIdx.x;
    const int tid = threadIdx.x;

    // Stage this image's 10KB logits table (640 float4s, coalesced).
    {
        const float4* ltab = (const float4*)(logits + img * LOGITS_PER_IMG);
        float4* stab = (float4*)s_logits;
        if (tid < LOGITS_PER_IMG / 4 - THREADS) {         // 640 - 512 = 128
            stab[tid] = ltab[tid];
            stab[tid + THREADS] = ltab[tid + THREADS];
        } else if (tid < LOGITS_PER_IMG / 4) {
            stab[tid] = ltab[tid];
        } else {
            stab[tid] = ltab[tid - (LOGITS_PER_IMG / 4 - THREADS) * 0];  // unreachable pad
        }
    }
    // simpler canonical staging for tids >= 128 handled above is wrong-prone;
    // redo plainly (compiler dedups):
    __syncthreads();
    {
        const float4* ltab = (const float4*)(logits + img * LOGITS_PER_IMG);
        float4* stab = (float4*)s_logits;
        for (int i = tid; i < LOGITS_PER_IMG / 4; i += THREADS)
            stab[i] = ltab[i];
    }
    __syncthreads();

    const int* seg_img = seg + img * PIX_PER_IMG;
    float4* out_img = out + img * VEC_PER_IMG;

    const int j0 = blk * VEC_PER_BLOCK + tid;     // first float4 index
    const int f0 = j0 << 2;                       // first float index

    // Single division per thread.
    int p = f0 / 5;
    int r = f0 - 5 * p;                           // 0..4

    // Phase 1: compute pixel indices for all iters, issue all seg loads.
    int pa[ITERS], ra[ITERS];
    int s0[ITERS], s1[ITERS];
#pragma unroll
    for (int it = 0; it < ITERS; ++it) {
        pa[it] = p;
        ra[it] = r;
        int p1 = p + 1;
        if (p1 >= PIX_PER_IMG) p1 = PIX_PER_IMG - 1;   // clamp (last pixel)
        s0[it] = __ldg(seg_img + p);
        s1[it] = __ldg(seg_img + p1);
        // advance: float index += 2048 = 5*409 + 3
        r += R_STEP;
        p += P_STEP;
        if (r >= 5) { r -= 5; p += 1; }
    }

    // Phase 2: gather from smem and store.
#pragma unroll
    for (int it = 0; it < ITERS; ++it) {
        int rr = ra[it];
        int m  = 5 - rr;                 // floats taken from pixel p (1..5)
        int b0 = s0[it] * WAY + rr;      // base for pixel p, channel rr
        int b1 = s1[it] * WAY + rr - 5;  // base for pixel p+1 (channel rr-5+k)

        float v[4];
#pragma unroll
        for (int k = 0; k < 4; ++k) {
            int base = (k < m) ? b0 : b1;
            v[k] = s_logits[base + k];
        }
        out_img[j0 + it * THREADS] = make_float4(v[0], v[1], v[2], v[3]);
    }
}

extern "C" void kernel_launch(void* const* d_in, const int* in_sizes, int n_in,
                              void* d_out, int out_size)
{
    const float* logits = (const float*)d_in[0];
    const int*   seg    = (const int*)d_in[1];
    float4*      out    = (float4*)d_out;

    dim3 grid(BLOCKS_PER_IMG, N_IMG);
    sp_gather_kernel3<<<grid, THREADS>>>(logits, seg, out);
}

// round 4
// speedup vs baseline: 1.0749x; 1.0749x over previous
#include <cuda_runtime.h>
#include <cuda_bf16.h>

// Gather: out[i, y, x, c] = logits[i * N_SP + segments[i, y, x], c]
//   logits:   [16*512, 5] fp32 (10 KB per image, staged in smem)
//   segments: [16, 512, 512] int32 (8 KB tile per block, staged in smem)
//   out:      [16, 512, 512, 5] fp32
//
// R4: hot loop is smem-only (gather LDS + coalesced STG.128). All global
// reads happen in one coalesced staging phase per block (1 int4 + ~1.25
// float4 per thread), eliminating the front-batched LDG pattern that causes
// cross-CTA L1tex-queue contention (R1/R3 evidence).

#define N_IMG 16
#define SIZE  512
#define N_SP  512
#define WAY   5
#define PIX_PER_IMG    (SIZE * SIZE)           // 262144
#define VEC_PER_IMG    (PIX_PER_IMG * WAY / 4) // 327680 float4
#define LOGITS_PER_IMG (N_SP * WAY)            // 2560 floats = 10 KB

#define THREADS 512
#define ITERS 5
#define VEC_PER_BLOCK (THREADS * ITERS)        // 2560 float4 = 10240 floats
#define PIX_PER_BLOCK (VEC_PER_BLOCK * 4 / WAY) // 2048 pixels exactly
#define BLOCKS_PER_IMG (VEC_PER_IMG / VEC_PER_BLOCK) // 128

// per-iteration float step = 4*THREADS = 2048 = 5*409 + 3
#define P_STEP 409
#define R_STEP 3

__global__ void __launch_bounds__(THREADS)
sp_gather_kernel4(const float* __restrict__ logits,
                  const int* __restrict__ seg,
                  float4* __restrict__ out)
{
    __shared__ __align__(16) float s_logits[LOGITS_PER_IMG];
    __shared__ __align__(16) int   s_seg[PIX_PER_BLOCK + 4];  // +pad for p+1 read

    const int img = blockIdx.y;
    const int blk = blockIdx.x;
    const int tid = threadIdx.x;

    // ---- Staging: all global reads, fully coalesced, low MLP ----
    {
        const float4* lt = (const float4*)(logits + img * LOGITS_PER_IMG);
        float4* st = (float4*)s_logits;
        st[tid] = lt[tid];                         // 512 of 640
        if (tid < LOGITS_PER_IMG / 4 - THREADS)    // remaining 128
            st[THREADS + tid] = lt[THREADS + tid];

        const int4* sg = (const int4*)(seg + img * PIX_PER_IMG
                                           + blk * PIX_PER_BLOCK);
        ((int4*)s_seg)[tid] = sg[tid];             // 2048 ints
        if (tid == 0) s_seg[PIX_PER_BLOCK] = 0;    // pad (value unused)
    }
    __syncthreads();

    // ---- Hot loop: smem gather + coalesced stores only ----
    const int jbase = blk * VEC_PER_BLOCK + tid;   // float4 index in image
    float4* out_img = out + img * VEC_PER_IMG;

    int floc = tid << 2;           // local float index, 0..2044
    int p = floc / 5;              // local pixel (small div, one umulhi)
    int r = floc - 5 * p;          // channel remainder 0..4

    float v[ITERS][4];
#pragma unroll
    for (int it = 0; it < ITERS; ++it) {
        int s0 = s_seg[p];
        int s1 = s_seg[p + 1];     // padded; unused when all 4 floats in p
        int m  = 5 - r;
        int b0 = s0 * WAY + r;
        int b1 = s1 * WAY + r - 5;
#pragma unroll
        for (int k = 0; k < 4; ++k)
            v[it][k] = s_logits[((k < m) ? b0 : b1) + k];

        r += R_STEP;
        p += P_STEP;
        if (r >= 5) { r -= 5; p += 1; }
    }

#pragma unroll
    for (int it = 0; it < ITERS; ++it)
        out_img[jbase + it * THREADS] =
            make_float4(v[it][0], v[it][1], v[it][2], v[it][3]);
}

extern "C" void kernel_launch(void* const* d_in, const int* in_sizes, int n_in,
                              void* d_out, int out_size)
{
    const float* logits = (const float*)d_in[0];
    const int*   seg    = (const int*)d_in[1];
    float4*      out    = (float4*)d_out;

    dim3 grid(BLOCKS_PER_IMG, N_IMG);
    sp_gather_kernel4<<<grid, THREADS>>>(logits, seg, out);
}